// round 17
// baseline (speedup 1.0000x reference)
#include <cuda_runtime.h>

// GAE fused single-pass scan, v17 = v16 with write-through output stores.
// R16 localized the systematic 7.8us kernel->wall gap to a post-kernel L2
// dirty-writeback tail (67MB outputs / ~8TB/s = 8.4us): __stcs leaves the
// output lines dirty in L2 at kernel end. __stwt streams them to DRAM
// DURING the kernel, overlapping with the read stream.

#define T_STEPS 4096
#define NENV    2048
#define NCHUNK  256
#define CHUNK   16

#define GAMMA_C 0.99f
#define GD_C    (0.99f * 0.95f)

__device__ float2 g_PS[NCHUNK * NENV];    // (P, S) aggregate per (chunk, env)
__device__ int    g_flag[NCHUNK * NENV];  // monotone per-run publish counter

// ---------------------------------------------------------------------------
__global__ void __launch_bounds__(256) gae_fused(
    const float* __restrict__ rewards,
    const float* __restrict__ values,
    const float* __restrict__ next_values,
    const int*   __restrict__ next_dones,
    float* __restrict__ adv,
    float* __restrict__ ret)
{
    __shared__ float sS[CHUNK * 256];                      // 16KB: local scan value
    __shared__ float sV[CHUNK * 256];                      // 16KB: values

    const int tid = threadIdx.x;
    const int e = blockIdx.x * blockDim.x + tid;           // env
    const int c = (NCHUNK - 1) - blockIdx.y;               // latest chunk = bid 0
    const int base = ((c + 1) * CHUNK - 1) * NENV + e;     // last timestep of chunk
    const int o = c * NENV + e;

    // Self-incrementing flag protocol: every slot ended the previous run at
    // the same count (published exactly once per run, only by its owner).
    const int f0 = ((volatile int*)g_flag)[o];
    const int fpub = f0 + 1;

    // ---- Phase A: local backward scan; S,V -> smem; inputs streamed once ----
    float g = 0.0f, p = 1.0f;
    unsigned int bits = 0u;
    bool alive = true;

    #pragma unroll
    for (int t = 0; t < CHUNK; t++) {                      // t=0 is LAST timestep
        const int idx = base - t * NENV;
        const int   dd = __ldcs(&next_dones[idx]);
        const float rr = __ldcs(&rewards[idx]);
        const float nv = __ldcs(&next_values[idx]);
        const float vv = __ldcs(&values[idx]);

        const float nd = dd ? 0.0f : 1.0f;
        g = (rr + GAMMA_C * nv * nd - vv) + GD_C * nd * g;
        p *= GD_C * nd;
        alive = alive && (dd == 0);
        if (alive) bits |= (1u << t);
        sS[t * 256 + tid] = g;
        sV[t * 256 + tid] = vv;
    }

    // ---- Publish aggregate ----
    g_PS[o] = make_float2(p, g);
    __threadfence();
    ((volatile int*)g_flag)[o] = fpub;

    // ---- Phase B: compose G from later chunks' aggregates.
    // dones ~ Bernoulli(0.5): 16-step chunk all-alive w.p. 2^-16 => accP hits
    // 0 after ~1 hop; walk is latency-trivial.
    float G = 0.0f;
    if (c < NCHUNK - 1) {
        float accP = 1.0f, accS = 0.0f;
        int w = o + NENV;                                  // next-later chunk, same env
        const int wend = NCHUNK * NENV;
        while (w < wend && accP > 1e-12f) {
            while (((volatile int*)g_flag)[w] != fpub) __nanosleep(40);
            __threadfence();                               // acquire
            const float2 ps = __ldcg(&g_PS[w]);
            accS += accP * ps.y;
            accP *= ps.x;
            w += NENV;
        }
        G = accS;
    }

    // ---- Phase C: fixup from smem; WRITE-THROUGH streaming stores so the
    //      output traffic hits DRAM during the kernel, not as an L2
    //      dirty-writeback tail after it. ----
    float pw = GD_C;
    #pragma unroll
    for (int t = 0; t < CHUNK; t++) {
        const int idx = base - t * NENV;
        const float fix = ((bits >> t) & 1u) ? pw * G : 0.0f;
        const float a = sS[t * 256 + tid] + fix;
        __stwt(&adv[idx], a);
        __stwt(&ret[idx], a + sV[t * 256 + tid]);
        pw *= GD_C;
    }
}

// ---------------------------------------------------------------------------
extern "C" void kernel_launch(void* const* d_in, const int* in_sizes, int n_in,
                              void* d_out, int out_size)
{
    const float* rewards     = (const float*)d_in[0];
    const float* values      = (const float*)d_in[1];
    const float* next_values = (const float*)d_in[2];
    const int*   next_dones  = (const int*)d_in[3];

    float* adv = (float*)d_out;
    float* ret = (float*)d_out + (size_t)T_STEPS * NENV;

    dim3 block(256);
    dim3 grid(NENV / 256, NCHUNK);   // (8, 256) = 2048 blocks
    gae_fused<<<grid, block>>>(rewards, values, next_values, next_dones, adv, ret);
}